// round 1
// baseline (speedup 1.0000x reference)
#include <cuda_runtime.h>
#include <cstddef>

#define BB 2
#define SS 2048
#define DD 1024
#define NH 16
#define DKH 64

// Scratch (static device globals; no runtime allocation)
__device__ float g_QK[(size_t)BB * SS * 2 * DD];   // [4096][2048]  Q cols 0..1023, K cols 1024..2047
__device__ float g_W2[(size_t)BB * DD * DD];       // [2][1024][1024]
__device__ float g_Y [(size_t)BB * SS * DD];       // [4096][1024]  pre-LN y

// ---------------------------------------------------------------------------
// Generic 128x128x8 fp32 SGEMM, 256 threads, 8x8 per-thread microtile.
// C[z] = alpha * (A[z] @ B[z]) + bias + res[z]   (bias/res optional)
// res uses ldc for its leading dimension.
// ---------------------------------------------------------------------------
__global__ __launch_bounds__(256)
void sgemm128(const float* __restrict__ A, int lda, size_t sAz,
              const float* __restrict__ Bm, int ldb, size_t sBz,
              float* __restrict__ C, int ldc, size_t sCz,
              const float* __restrict__ bias,
              const float* __restrict__ res, size_t sRz,
              float alpha, int Kdim)
{
    A  += (size_t)blockIdx.z * sAz;
    Bm += (size_t)blockIdx.z * sBz;
    C  += (size_t)blockIdx.z * sCz;
    if (res) res += (size_t)blockIdx.z * sRz;

    __shared__ float As[8][128];   // transposed A tile: As[k][m]
    __shared__ float Bs[8][128];   // Bs[k][n]

    const int tid = threadIdx.x;
    const int m0 = blockIdx.y * 128, n0 = blockIdx.x * 128;
    const int tx = tid & 15, ty = tid >> 4;

    // A tile load: 128 rows x 8 cols, float4 per thread: row=tid/2, k-off=(tid&1)*4
    const int arow = tid >> 1;
    const int acol = (tid & 1) * 4;
    // B tile load: 8 rows x 128 cols: row=tid/32, col=(tid&31)*4
    const int brow = tid >> 5;
    const int bcol = (tid & 31) * 4;

    float acc[8][8];
#pragma unroll
    for (int i = 0; i < 8; ++i)
#pragma unroll
        for (int j = 0; j < 8; ++j) acc[i][j] = 0.f;

    for (int k0 = 0; k0 < Kdim; k0 += 8) {
        float4 av = *(const float4*)(A + (size_t)(m0 + arow) * lda + k0 + acol);
        As[acol + 0][arow] = av.x;
        As[acol + 1][arow] = av.y;
        As[acol + 2][arow] = av.z;
        As[acol + 3][arow] = av.w;
        *(float4*)(&Bs[brow][bcol]) =
            *(const float4*)(Bm + (size_t)(k0 + brow) * ldb + n0 + bcol);
        __syncthreads();

#pragma unroll
        for (int kk = 0; kk < 8; ++kk) {
            float ra[8], rb[8];
            *(float4*)(ra)     = *(const float4*)(&As[kk][ty * 8]);
            *(float4*)(ra + 4) = *(const float4*)(&As[kk][ty * 8 + 4]);
            *(float4*)(rb)     = *(const float4*)(&Bs[kk][tx * 8]);
            *(float4*)(rb + 4) = *(const float4*)(&Bs[kk][tx * 8 + 4]);
#pragma unroll
            for (int i = 0; i < 8; ++i)
#pragma unroll
                for (int j = 0; j < 8; ++j)
                    acc[i][j] = fmaf(ra[i], rb[j], acc[i][j]);
        }
        __syncthreads();
    }

    // Epilogue
#pragma unroll
    for (int i = 0; i < 8; ++i) {
        const int m = m0 + ty * 8 + i;
        const int n = n0 + tx * 8;
        float* crow = C + (size_t)m * ldc + n;
        const float* rrow = res ? res + (size_t)m * ldc + n : nullptr;
#pragma unroll
        for (int j = 0; j < 8; j += 4) {
            float4 v;
            v.x = acc[i][j + 0] * alpha;
            v.y = acc[i][j + 1] * alpha;
            v.z = acc[i][j + 2] * alpha;
            v.w = acc[i][j + 3] * alpha;
            if (bias) {
                v.x += bias[n + j + 0]; v.y += bias[n + j + 1];
                v.z += bias[n + j + 2]; v.w += bias[n + j + 3];
            }
            if (rrow) {
                v.x += rrow[j + 0]; v.y += rrow[j + 1];
                v.z += rrow[j + 2]; v.w += rrow[j + 3];
            }
            *(float4*)(crow + j) = v;
        }
    }
}

// ---------------------------------------------------------------------------
// K2: W2[b, n*64+kl, d'] = sum_j K[b,j,n*64+kl] * w_fc[j*16+n, d']
// 32 GEMMs (b,n): M=64, N=1024 (tiled 64), Kdim(j)=2048. 64x64x16 tile.
// ---------------------------------------------------------------------------
__global__ __launch_bounds__(256)
void k2_kernel(const float* __restrict__ QK, const float* __restrict__ wfc,
               float* __restrict__ W2)
{
    const int bn = blockIdx.y;            // 0..31
    const int b = bn >> 4, n = bn & 15;
    const int d0 = blockIdx.x * 64;

    __shared__ float As[16][64];          // As[jj][kl]
    __shared__ float Bs[16][64];          // Bs[jj][dl]

    const int tid = threadIdx.x;
    const int tx = tid & 15, ty = tid >> 4;
    const int lrow = tid >> 4;            // 0..15
    const int lcol = (tid & 15) * 4;      // 0..60

    const float* Abase = QK + (size_t)b * SS * 2 * DD + DD + n * DKH; // K part, row stride 2048
    const float* Bbase = wfc + (size_t)n * DD;                        // rows j*16+n, stride 16*1024

    float acc[4][4];
#pragma unroll
    for (int i = 0; i < 4; ++i)
#pragma unroll
        for (int j = 0; j < 4; ++j) acc[i][j] = 0.f;

    for (int j0 = 0; j0 < SS; j0 += 16) {
        *(float4*)(&As[lrow][lcol]) =
            *(const float4*)(Abase + (size_t)(j0 + lrow) * (2 * DD) + lcol);
        *(float4*)(&Bs[lrow][lcol]) =
            *(const float4*)(Bbase + (size_t)(j0 + lrow) * (NH * DD) + d0 + lcol);
        __syncthreads();

#pragma unroll
        for (int kk = 0; kk < 16; ++kk) {
            float4 ra = *(const float4*)(&As[kk][ty * 4]);
            float4 rb = *(const float4*)(&Bs[kk][tx * 4]);
            float a[4] = {ra.x, ra.y, ra.z, ra.w};
            float bb[4] = {rb.x, rb.y, rb.z, rb.w};
#pragma unroll
            for (int i = 0; i < 4; ++i)
#pragma unroll
                for (int j = 0; j < 4; ++j)
                    acc[i][j] = fmaf(a[i], bb[j], acc[i][j]);
        }
        __syncthreads();
    }

    float* Cb = W2 + ((size_t)b * DD + n * DKH) * DD + d0;
#pragma unroll
    for (int i = 0; i < 4; ++i) {
        float4 v = make_float4(acc[i][0], acc[i][1], acc[i][2], acc[i][3]);
        *(float4*)(Cb + (size_t)(ty * 4 + i) * DD + tx * 4) = v;
    }
}

// ---------------------------------------------------------------------------
// K4: row-wise LayerNorm over 1024 elements. One block per row, 256 threads.
// ---------------------------------------------------------------------------
__global__ __launch_bounds__(256)
void ln_kernel(const float* __restrict__ Y, const float* __restrict__ gamma,
               const float* __restrict__ beta, float* __restrict__ out)
{
    const int row = blockIdx.x;
    const int tid = threadIdx.x;
    const float4* y4 = (const float4*)(Y + (size_t)row * DD);
    float4 v = y4[tid];

    __shared__ float sb[8];

    float s = v.x + v.y + v.z + v.w;
#pragma unroll
    for (int o = 16; o; o >>= 1) s += __shfl_xor_sync(0xffffffffu, s, o);
    if ((tid & 31) == 0) sb[tid >> 5] = s;
    __syncthreads();
    float tot = 0.f;
#pragma unroll
    for (int i = 0; i < 8; ++i) tot += sb[i];
    const float mean = tot * (1.0f / DD);
    __syncthreads();

    const float dx = v.x - mean, dy = v.y - mean, dz = v.z - mean, dw = v.w - mean;
    float ss = dx * dx + dy * dy + dz * dz + dw * dw;
#pragma unroll
    for (int o = 16; o; o >>= 1) ss += __shfl_xor_sync(0xffffffffu, ss, o);
    if ((tid & 31) == 0) sb[tid >> 5] = ss;
    __syncthreads();
    float tot2 = 0.f;
#pragma unroll
    for (int i = 0; i < 8; ++i) tot2 += sb[i];
    const float inv = rsqrtf(tot2 * (1.0f / DD) + 1e-5f);

    const float4 g = ((const float4*)gamma)[tid];
    const float4 bt = ((const float4*)beta)[tid];
    float4 o4;
    o4.x = g.x * dx * inv + bt.x;
    o4.y = g.y * dy * inv + bt.y;
    o4.z = g.z * dz * inv + bt.z;
    o4.w = g.w * dw * inv + bt.w;
    ((float4*)(out + (size_t)row * DD))[tid] = o4;
}

// ---------------------------------------------------------------------------
extern "C" void kernel_launch(void* const* d_in, const int* in_sizes, int n_in,
                              void* d_out, int out_size)
{
    const float* x      = (const float*)d_in[0];
    const float* w_qkv  = (const float*)d_in[1];
    const float* b_qkv  = (const float*)d_in[2];
    const float* w_fc   = (const float*)d_in[3];
    const float* b_fc   = (const float*)d_in[4];
    const float* gamma  = (const float*)d_in[5];
    const float* beta   = (const float*)d_in[6];
    float* out = (float*)d_out;

    float *QK, *W2, *Y;
    cudaGetSymbolAddress((void**)&QK, g_QK);
    cudaGetSymbolAddress((void**)&W2, g_W2);
    cudaGetSymbolAddress((void**)&Y,  g_Y);

    // K1: QK = x @ w_qkv[:, :2048] + b_qkv[:2048]   (M=4096, N=2048, K=1024)
    {
        dim3 grid(2 * DD / 128, (BB * SS) / 128, 1);
        sgemm128<<<grid, 256>>>(x, DD, 0,
                                w_qkv, 3 * DD, 0,
                                QK, 2 * DD, 0,
                                b_qkv, nullptr, 0,
                                1.0f, DD);
    }

    // K2: W2[b] per-head K^T @ w_fc slices
    {
        dim3 grid(DD / 64, BB * NH, 1);
        k2_kernel<<<grid, 256>>>(QK, w_fc, W2);
    }

    // K3: Y[b] = 0.125 * Q[b] @ W2[b] + b_fc + x[b]   (M=2048, N=1024, K=1024) x2
    {
        dim3 grid(DD / 128, SS / 128, BB);
        sgemm128<<<grid, 256>>>(QK, 2 * DD, (size_t)SS * 2 * DD,
                                W2, DD, (size_t)DD * DD,
                                Y, DD, (size_t)SS * DD,
                                b_fc, x, (size_t)SS * DD,
                                0.125f, DD);
    }

    // K4: LayerNorm
    ln_kernel<<<BB * SS, 256>>>(Y, gamma, beta, out);
}

// round 3
// speedup vs baseline: 2.3168x; 2.3168x over previous
#include <cuda_runtime.h>
#include <cuda_bf16.h>
#include <cstddef>
#include <cstdint>

#define BB 2
#define SS 2048
#define DD 1024
#define NH 16
#define DKH 64

// Scratch (static device globals; no runtime allocation)
__device__ float g_QK[(size_t)BB * SS * 2 * DD];   // [4096][2048]  Q cols 0..1023, K cols 1024..2047
__device__ float g_W2[(size_t)BB * DD * DD];       // [2][1024][1024]
__device__ float g_Y [(size_t)BB * SS * DD];       // [4096][1024]  pre-LN y

// ---------------------------------------------------------------------------
// helpers
// ---------------------------------------------------------------------------
__device__ __forceinline__ void ldm4(uint32_t* r, const unsigned short* p) {
    uint32_t a = (uint32_t)__cvta_generic_to_shared(p);
    asm volatile("ldmatrix.sync.aligned.m8n8.x4.shared.b16 {%0,%1,%2,%3}, [%4];"
                 : "=r"(r[0]), "=r"(r[1]), "=r"(r[2]), "=r"(r[3]) : "r"(a));
}
__device__ __forceinline__ void ldm4t(uint32_t* r, const unsigned short* p) {
    uint32_t a = (uint32_t)__cvta_generic_to_shared(p);
    asm volatile("ldmatrix.sync.aligned.m8n8.x4.trans.shared.b16 {%0,%1,%2,%3}, [%4];"
                 : "=r"(r[0]), "=r"(r[1]), "=r"(r[2]), "=r"(r[3]) : "r"(a));
}
__device__ __forceinline__ void mma16816(float* c, const uint32_t* a, uint32_t b0, uint32_t b1) {
    asm volatile(
        "mma.sync.aligned.m16n8k16.row.col.f32.bf16.bf16.f32 "
        "{%0,%1,%2,%3},{%4,%5,%6,%7},{%8,%9},{%0,%1,%2,%3};"
        : "+f"(c[0]), "+f"(c[1]), "+f"(c[2]), "+f"(c[3])
        : "r"(a[0]), "r"(a[1]), "r"(a[2]), "r"(a[3]), "r"(b0), "r"(b1));
}

// split pair: hi = truncated top-16-bits of fp32 (exact bf16), lo = bf16_rn(x - hi)
__device__ __forceinline__ void split2(float x, float y, uint32_t& hi2, uint32_t& lo2) {
    uint32_t ux = __float_as_uint(x) & 0xffff0000u;
    uint32_t uy = __float_as_uint(y) & 0xffff0000u;
    hi2 = uy | (ux >> 16);
    float lx = x - __uint_as_float(ux);
    float ly = y - __uint_as_float(uy);
    __nv_bfloat162 l = __floats2bfloat162_rn(lx, ly);
    lo2 = *reinterpret_cast<uint32_t*>(&l);
}

__device__ __forceinline__ unsigned short bf16_bits(float f) {
    __nv_bfloat16 b = __float2bfloat16(f);
    return *reinterpret_cast<unsigned short*>(&b);
}

// ---------------------------------------------------------------------------
// Unified bf16-split tensor-core GEMM.
// MODE 0 : K1  QK = x @ w_qkv[:, :2048] + b_qkv          (M=4096,N=2048,K=1024)
// MODE 1 : K2  W2[b,n] = K_slice^T @ w_fc_slice          (M=64,  N=1024,K=2048) x32
// MODE 2 : K3  Y[b] = 0.125*Q[b]@W2[b] + b_fc + x[b]     (M=2048,N=1024,K=1024) x2
// ---------------------------------------------------------------------------
template <int MODE>
__global__ __launch_bounds__(256) void gemm_mma(
    const float* __restrict__ A0, const float* __restrict__ B0,
    float* __restrict__ C0, const float* __restrict__ bias,
    const float* __restrict__ res0)
{
    constexpr bool TRA = (MODE == 1);
    constexpr int  BM  = TRA ? 64 : 128;
    constexpr int  KD  = TRA ? 2048 : 1024;
    constexpr int  WN  = TRA ? 32 : 64;      // warp n-extent
    constexpr int  NT  = WN / 16;            // n16 tiles per warp
    constexpr int  AP  = 40;                 // A smem row pitch (halfwords)
    constexpr int  BP  = 136;                // B smem row pitch (halfwords)

    __shared__ __align__(16) unsigned short AhS[BM * AP];
    __shared__ __align__(16) unsigned short AlS[BM * AP];
    __shared__ __align__(16) unsigned short BhS[32 * BP];
    __shared__ __align__(16) unsigned short BlS[32 * BP];

    const int tid = threadIdx.x;
    const int lane = tid & 31;
    const int w = tid >> 5;

    const float* A; const float* Bm; float* C; const float* res = nullptr;
    int lda, ldb, ldc, m0;
    float alpha;
    if constexpr (MODE == 0) {
        A = A0; lda = DD; Bm = B0; ldb = 3 * DD; C = C0; ldc = 2 * DD;
        alpha = 1.f; m0 = blockIdx.y * 128;
    } else if constexpr (MODE == 1) {
        const int z = blockIdx.y, b = z >> 4, n = z & 15;
        A = A0 + (size_t)b * SS * 2 * DD + DD + n * DKH; lda = 2 * DD;  // [k=j][m=kl]
        Bm = B0 + (size_t)n * DD; ldb = NH * DD;
        C = C0 + ((size_t)b * DD + n * DKH) * DD; ldc = DD;
        alpha = 1.f; m0 = 0;
    } else {
        const int z = blockIdx.z;
        A = A0 + (size_t)z * SS * 2 * DD; lda = 2 * DD;
        Bm = B0 + (size_t)z * DD * DD; ldb = DD;
        C = C0 + (size_t)z * SS * DD; ldc = DD;
        res = res0 + (size_t)z * SS * DD;
        alpha = 0.125f; m0 = blockIdx.y * 128;
    }
    const int n0 = blockIdx.x * 128;

    // warp tile origin
    const int wm = TRA ? (w & 1) * 32 : (w & 3) * 32;
    const int wn = TRA ? (w >> 1) * 32 : (w >> 2) * 64;

    // fragment lane offsets
    const int a_r = lane & 15;
    const int a_c = (lane >> 4) << 3;
    const int b_r = (lane & 7) + ((lane >> 3) & 1) * 8;
    const int b_c = (lane >> 4) << 3;

    float acc[2][2 * NT][4];
#pragma unroll
    for (int i = 0; i < 2; ++i)
#pragma unroll
        for (int j = 0; j < 2 * NT; ++j)
#pragma unroll
            for (int q = 0; q < 4; ++q) acc[i][j][q] = 0.f;

    constexpr int NA = TRA ? 2 : 4;   // float4 per thread for A tile
    float4 pa[NA], pb[4];

    auto loadA = [&](int k0) {
        if constexpr (!TRA) {
#pragma unroll
            for (int i = 0; i < NA; ++i) {
                int id = i * 256 + tid, r = id >> 3, c = (id & 7) * 4;
                pa[i] = *(const float4*)(A + (size_t)(m0 + r) * lda + k0 + c);
            }
        } else {
#pragma unroll
            for (int i = 0; i < NA; ++i) {
                int id = i * 256 + tid, kr = id >> 4, mc = (id & 15) * 4;
                pa[i] = *(const float4*)(A + (size_t)(k0 + kr) * lda + mc);
            }
        }
    };
    auto loadB = [&](int k0) {
#pragma unroll
        for (int i = 0; i < 4; ++i) {
            int id = i * 256 + tid, r = id >> 5, c = (id & 31) * 4;
            pb[i] = *(const float4*)(Bm + (size_t)(k0 + r) * ldb + n0 + c);
        }
    };
    auto storeTiles = [&]() {
        if constexpr (!TRA) {
#pragma unroll
            for (int i = 0; i < NA; ++i) {
                int id = i * 256 + tid, r = id >> 3, c = (id & 7) * 4;
                uint32_t h0, l0, h1, l1;
                split2(pa[i].x, pa[i].y, h0, l0);
                split2(pa[i].z, pa[i].w, h1, l1);
                *(uint2*)&AhS[r * AP + c] = make_uint2(h0, h1);
                *(uint2*)&AlS[r * AP + c] = make_uint2(l0, l1);
            }
        } else {
            // transpose path: A tile arrives [k][m], store as [m][k]
#pragma unroll
            for (int i = 0; i < NA; ++i) {
                int id = i * 256 + tid, kr = id >> 4, mc = (id & 15) * 4;
                float e[4] = {pa[i].x, pa[i].y, pa[i].z, pa[i].w};
#pragma unroll
                for (int j = 0; j < 4; ++j) {
                    uint32_t u = __float_as_uint(e[j]) & 0xffff0000u;
                    float lf = e[j] - __uint_as_float(u);
                    AhS[(mc + j) * AP + kr] = (unsigned short)(u >> 16);
                    AlS[(mc + j) * AP + kr] = bf16_bits(lf);
                }
            }
        }
#pragma unroll
        for (int i = 0; i < 4; ++i) {
            int id = i * 256 + tid, r = id >> 5, c = (id & 31) * 4;
            uint32_t h0, l0, h1, l1;
            split2(pb[i].x, pb[i].y, h0, l0);
            split2(pb[i].z, pb[i].w, h1, l1);
            *(uint2*)&BhS[r * BP + c] = make_uint2(h0, h1);
            *(uint2*)&BlS[r * BP + c] = make_uint2(l0, l1);
        }
    };

    loadA(0); loadB(0);

    for (int k0 = 0; k0 < KD; k0 += 32) {
        storeTiles();
        __syncthreads();
        if (k0 + 32 < KD) { loadA(k0 + 32); loadB(k0 + 32); }

#pragma unroll
        for (int kk = 0; kk < 32; kk += 16) {
            uint32_t ah[2][4], al[2][4], bh[NT][4], bl[NT][4];
#pragma unroll
            for (int mt = 0; mt < 2; ++mt) {
                const int ao = (wm + mt * 16 + a_r) * AP + kk + a_c;
                ldm4(ah[mt], &AhS[ao]);
                ldm4(al[mt], &AlS[ao]);
            }
#pragma unroll
            for (int nt = 0; nt < NT; ++nt) {
                const int bo = (kk + b_r) * BP + wn + nt * 16 + b_c;
                ldm4t(bh[nt], &BhS[bo]);
                ldm4t(bl[nt], &BlS[bo]);
            }
#pragma unroll
            for (int mt = 0; mt < 2; ++mt)
#pragma unroll
                for (int j = 0; j < 2 * NT; ++j) {
                    const uint32_t* Bh = &bh[j >> 1][(j & 1) * 2];
                    const uint32_t* Bl = &bl[j >> 1][(j & 1) * 2];
                    mma16816(acc[mt][j], ah[mt], Bh[0], Bh[1]);  // hi*hi
                    mma16816(acc[mt][j], ah[mt], Bl[0], Bl[1]);  // hi*lo
                    mma16816(acc[mt][j], al[mt], Bh[0], Bh[1]);  // lo*hi
                }
        }
        __syncthreads();
    }

    // epilogue
    const int gid = lane >> 2, tig = lane & 3;
#pragma unroll
    for (int mt = 0; mt < 2; ++mt)
#pragma unroll
        for (int j = 0; j < 2 * NT; ++j) {
            const int r0 = m0 + wm + mt * 16 + gid;
            const int c = n0 + wn + j * 8 + tig * 2;
            float2 v0 = make_float2(acc[mt][j][0] * alpha, acc[mt][j][1] * alpha);
            float2 v1 = make_float2(acc[mt][j][2] * alpha, acc[mt][j][3] * alpha);
            if constexpr (MODE != 1) {
                v0.x += bias[c]; v0.y += bias[c + 1];
                v1.x += bias[c]; v1.y += bias[c + 1];
            }
            if constexpr (MODE == 2) {
                const float* rr0 = res + (size_t)r0 * ldc + c;
                const float* rr1 = res + (size_t)(r0 + 8) * ldc + c;
                v0.x += rr0[0]; v0.y += rr0[1];
                v1.x += rr1[0]; v1.y += rr1[1];
            }
            *(float2*)(C + (size_t)r0 * ldc + c) = v0;
            *(float2*)(C + (size_t)(r0 + 8) * ldc + c) = v1;
        }
}

// ---------------------------------------------------------------------------
// K4: row-wise LayerNorm over 1024 elements. One block per row, 256 threads.
// ---------------------------------------------------------------------------
__global__ __launch_bounds__(256)
void ln_kernel(const float* __restrict__ Y, const float* __restrict__ gamma,
               const float* __restrict__ beta, float* __restrict__ out)
{
    const int row = blockIdx.x;
    const int tid = threadIdx.x;
    const float4* y4 = (const float4*)(Y + (size_t)row * DD);
    float4 v = y4[tid];

    __shared__ float sb[8];

    float s = v.x + v.y + v.z + v.w;
#pragma unroll
    for (int o = 16; o; o >>= 1) s += __shfl_xor_sync(0xffffffffu, s, o);
    if ((tid & 31) == 0) sb[tid >> 5] = s;
    __syncthreads();
    float tot = 0.f;
#pragma unroll
    for (int i = 0; i < 8; ++i) tot += sb[i];
    const float mean = tot * (1.0f / DD);
    __syncthreads();

    const float dx = v.x - mean, dy = v.y - mean, dz = v.z - mean, dw = v.w - mean;
    float ss = dx * dx + dy * dy + dz * dz + dw * dw;
#pragma unroll
    for (int o = 16; o; o >>= 1) ss += __shfl_xor_sync(0xffffffffu, ss, o);
    if ((tid & 31) == 0) sb[tid >> 5] = ss;
    __syncthreads();
    float tot2 = 0.f;
#pragma unroll
    for (int i = 0; i < 8; ++i) tot2 += sb[i];
    const float inv = rsqrtf(tot2 * (1.0f / DD) + 1e-5f);

    const float4 g = ((const float4*)gamma)[tid];
    const float4 bt = ((const float4*)beta)[tid];
    float4 o4;
    o4.x = g.x * dx * inv + bt.x;
    o4.y = g.y * dy * inv + bt.y;
    o4.z = g.z * dz * inv + bt.z;
    o4.w = g.w * dw * inv + bt.w;
    ((float4*)(out + (size_t)row * DD))[tid] = o4;
}

// ---------------------------------------------------------------------------
extern "C" void kernel_launch(void* const* d_in, const int* in_sizes, int n_in,
                              void* d_out, int out_size)
{
    const float* x      = (const float*)d_in[0];
    const float* w_qkv  = (const float*)d_in[1];
    const float* b_qkv  = (const float*)d_in[2];
    const float* w_fc   = (const float*)d_in[3];
    const float* b_fc   = (const float*)d_in[4];
    const float* gamma  = (const float*)d_in[5];
    const float* beta   = (const float*)d_in[6];
    float* out = (float*)d_out;

    float *QK, *W2, *Y;
    cudaGetSymbolAddress((void**)&QK, g_QK);
    cudaGetSymbolAddress((void**)&W2, g_W2);
    cudaGetSymbolAddress((void**)&Y,  g_Y);

    // K1: QK = x @ w_qkv[:, :2048] + b_qkv[:2048]
    gemm_mma<0><<<dim3(2 * DD / 128, (BB * SS) / 128), 256>>>(x, w_qkv, QK, b_qkv, nullptr);

    // K2: W2[b,(n)] = K_slice^T @ w_fc_slice
    gemm_mma<1><<<dim3(DD / 128, BB * NH), 256>>>(QK, w_fc, W2, nullptr, nullptr);

    // K3: Y[b] = 0.125 * Q[b] @ W2[b] + b_fc + x[b]
    gemm_mma<2><<<dim3(DD / 128, SS / 128, BB), 256>>>(QK, W2, Y, b_fc, x);

    // K4: LayerNorm
    ln_kernel<<<BB * SS, 256>>>(Y, gamma, beta, out);
}